// round 1
// baseline (speedup 1.0000x reference)
#include <cuda_runtime.h>
#include <math.h>

// Problem constants (fixed shapes for this bench)
#define Nn   16
#define Pp   866
#define CIN  1280
#define Cc   512
#define HWs  64          // h*w = 8*8
#define NOUT 10          // 2 + DEPTH
#define PW   5130        // (Cc+1)*NOUT floats per (n,p)
#define PWU  2565        // PW/2 (as float2 / ull)
#define BN_EPS 0.001f

typedef unsigned long long ull;

// scratch: f = silu(bn(conv(features)))  [n][c][hw]
__device__ float g_f[Nn * Cc * HWs];

// ---------- f32x2 helpers ----------
__device__ __forceinline__ ull splat2(float x) {
    ull r; asm("mov.b64 %0, {%1, %1};" : "=l"(r) : "f"(x)); return r;
}
__device__ __forceinline__ void fma2(ull &d, ull a, ull b) {
    asm("fma.rn.f32x2 %0, %1, %2, %0;" : "+l"(d) : "l"(a), "l"(b));
}
__device__ __forceinline__ void add2(ull &d, ull a) {
    asm("add.rn.f32x2 %0, %0, %1;" : "+l"(d) : "l"(a));
}
__device__ __forceinline__ float2 unpack2(ull u) {
    float2 f; asm("mov.b64 {%0, %1}, %2;" : "=f"(f.x), "=f"(f.y) : "l"(u)); return f;
}

// =====================================================================
// Kernel 1: f[n][c][hw] = silu( scale[c]*(features . conv_w) + bias[c] )
// grid (16 cgroups of 32c, 16 n), 256 threads = 64 hw x 4 csub, 8 c/thread
// =====================================================================
__global__ void __launch_bounds__(256)
conv_bn_silu_kernel(const float* __restrict__ feat,
                    const float* __restrict__ convw,
                    const float* __restrict__ gamma,
                    const float* __restrict__ beta,
                    const float* __restrict__ mean,
                    const float* __restrict__ var)
{
    const int cg = blockIdx.x;         // 0..15 (32 channels each)
    const int n  = blockIdx.y;         // 0..15
    const int t  = threadIdx.x;
    const int hw = t & 63;
    const int csub = t >> 6;           // 0..3

    __shared__ __align__(16) float sf[32 * 64];       // [k][hw]
    __shared__ __align__(16) float swt[32 * 34];      // [k][c] padded stride 34

    ull acc[4];
    acc[0] = acc[1] = acc[2] = acc[3] = 0ull;

    const float* fsrc = feat + (size_t)n * CIN * HWs;
    const float* wsrc = convw + (size_t)cg * 32 * CIN;

    for (int kb = 0; kb < CIN; kb += 32) {
        __syncthreads();
        // stage features chunk [32k][64hw], coalesced
        #pragma unroll
        for (int i = 0; i < 8; i++) {
            int lin = t + 256 * i;                 // 0..2047
            sf[lin] = fsrc[(size_t)(kb + (lin >> 6)) * HWs + (lin & 63)];
        }
        // stage conv_w chunk transposed: swt[k*34 + c]
        #pragma unroll
        for (int i = 0; i < 4; i++) {
            int lin = t + 256 * i;                 // 0..1023
            int ci = lin >> 5, ki = lin & 31;
            swt[ki * 34 + ci] = wsrc[(size_t)ci * CIN + kb + ki];
        }
        __syncthreads();
        #pragma unroll
        for (int kk = 0; kk < 32; kk++) {
            ull fv2 = splat2(sf[kk * 64 + hw]);
            const ull* wr = (const ull*)(swt + kk * 34 + csub * 8);
            fma2(acc[0], fv2, wr[0]);
            fma2(acc[1], fv2, wr[1]);
            fma2(acc[2], fv2, wr[2]);
            fma2(acc[3], fv2, wr[3]);
        }
    }

    const int c0 = cg * 32 + csub * 8;
    #pragma unroll
    for (int j = 0; j < 4; j++) {
        float2 v = unpack2(acc[j]);
        int c = c0 + 2 * j;
        // channel c
        {
            float sc = gamma[c] * rsqrtf(var[c] + BN_EPS);
            float bi = beta[c] - mean[c] * sc;
            float a = v.x * sc + bi;
            a = a / (1.0f + expf(-a));            // silu
            g_f[((size_t)n * Cc + c) * HWs + hw] = a;
        }
        // channel c+1
        {
            float sc = gamma[c + 1] * rsqrtf(var[c + 1] + BN_EPS);
            float bi = beta[c + 1] - mean[c + 1] * sc;
            float a = v.y * sc + bi;
            a = a / (1.0f + expf(-a));
            g_f[((size_t)n * Cc + c + 1) * HWs + hw] = a;
        }
    }
}

// =====================================================================
// Kernel 2: per (n, 4 p's): logits[10][64] GEMM (K=512) + full epilogue
// 128 threads = 64 hw x 2-way K split. Dynamic smem: 4x5130 w + combine + rb
// =====================================================================
#define SW_BYTES   (4 * PW * 4)                 // 82080
#define COMB_BYTES (64 * 4 * 5 * 8)             // 10240
#define RB_BYTES   (32 * 4)
#define SMEM2_BYTES (SW_BYTES + COMB_BYTES + RB_BYTES)

template<int NV, bool ISMAX>
__device__ __forceinline__ void block_red(float* v, float* rb)
{
    const int lane = threadIdx.x & 31;
    const int wid  = threadIdx.x >> 5;
    #pragma unroll
    for (int o = 16; o > 0; o >>= 1) {
        #pragma unroll
        for (int i = 0; i < NV; i++) {
            float other = __shfl_xor_sync(0xffffffffu, v[i], o);
            v[i] = ISMAX ? fmaxf(v[i], other) : (v[i] + other);
        }
    }
    if (lane == 0) {
        #pragma unroll
        for (int i = 0; i < NV; i++) rb[i * 4 + wid] = v[i];
    }
    __syncthreads();
    #pragma unroll
    for (int i = 0; i < NV; i++) {
        float a = rb[i * 4 + 0], b = rb[i * 4 + 1];
        float c = rb[i * 4 + 2], d = rb[i * 4 + 3];
        v[i] = ISMAX ? fmaxf(fmaxf(a, b), fmaxf(c, d)) : ((a + b) + (c + d));
    }
    __syncthreads();
}

__global__ void __launch_bounds__(128)
head_kernel(const float* __restrict__ weights, float* __restrict__ out)
{
    const int pb = blockIdx.x;          // 0..216
    const int n  = blockIdx.y;          // 0..15
    const int p0 = pb * 4;
    const int t  = threadIdx.x;
    const int hw = t & 63;
    const int ks = t >> 6;              // 0 or 1 (K split)

    extern __shared__ __align__(16) char smem[];
    float* sw   = (float*)smem;                               // 4*5130 floats
    ull*   comb = (ull*)(smem + SW_BYTES);                    // 64*4*5 ull
    float* rb   = (float*)(smem + SW_BYTES + COMB_BYTES);     // 32 floats

    // ---- stage 4 p's worth of weights into smem (float2 loads) ----
    {
        const ull* wg  = (const ull*)weights;
        ull*       swu = (ull*)sw;
        for (int idx = t; idx < 4 * PWU; idx += 128) {
            int pi = idx / PWU;
            int r  = idx - pi * PWU;
            int p  = p0 + pi;
            if (p < Pp)
                swu[pi * PWU + r] = wg[(size_t)(n * Pp + p) * PWU + r];
        }
    }
    __syncthreads();

    // ---- main GEMM loop ----
    ull acc[4][5];
    #pragma unroll
    for (int pi = 0; pi < 4; pi++)
        #pragma unroll
        for (int j = 0; j < 5; j++) acc[pi][j] = 0ull;

    const float* fb = g_f + ((size_t)n * Cc + ks * 256) * HWs + hw;
    const int kbase = ks * 256;

    #pragma unroll 4
    for (int kk = 0; kk < 256; kk++) {
        float fv = __ldg(fb + kk * 64);
        ull fv2 = splat2(fv);
        const int wo = (kbase + kk) * NOUT;
        #pragma unroll
        for (int pi = 0; pi < 4; pi++) {
            const ull* wr = (const ull*)(sw + pi * PW + wo);
            fma2(acc[pi][0], fv2, wr[0]);
            fma2(acc[pi][1], fv2, wr[1]);
            fma2(acc[pi][2], fv2, wr[2]);
            fma2(acc[pi][3], fv2, wr[3]);
            fma2(acc[pi][4], fv2, wr[4]);
        }
    }

    // ---- combine K splits ----
    if (ks == 1) {
        #pragma unroll
        for (int pi = 0; pi < 4; pi++)
            #pragma unroll
            for (int j = 0; j < 5; j++)
                comb[(hw * 4 + pi) * 5 + j] = acc[pi][j];
    }
    __syncthreads();
    if (ks == 0) {
        #pragma unroll
        for (int pi = 0; pi < 4; pi++)
            #pragma unroll
            for (int j = 0; j < 5; j++)
                add2(acc[pi][j], comb[(hw * 4 + pi) * 5 + j]);
    }

    // ---- epilogue per p ----
    const float inv7 = 1.0f / 7.0f;
    const float xsv = (float)(hw & 7) * inv7;
    const float ysv = (float)(hw >> 3) * inv7;
    const bool act = (ks == 0);
    const float NEGINF = -INFINITY;
    const int pc = min(4, Pp - p0);

    for (int pi = 0; pi < 4; pi++) {
        if (pi >= pc) break;    // uniform across block

        float l[10];
        if (act) {
            #pragma unroll
            for (int j = 0; j < 5; j++) {
                float2 v = unpack2(acc[pi][j]);
                l[2 * j] = v.x; l[2 * j + 1] = v.y;
            }
            const float* bb = sw + pi * PW + Cc * NOUT;   // bias row (k = 512)
            #pragma unroll
            for (int c = 0; c < 10; c++) l[c] += bb[c];
        }

        // --- xy heatmap softmax -> cx, cy ---
        float m1[1]; m1[0] = act ? l[1] : NEGINF;
        block_red<1, true>(m1, rb);
        float e1 = act ? expf(l[1] - m1[0]) : 0.0f;
        float s3[3] = { e1, e1 * xsv, e1 * ysv };
        block_red<3, false>(s3, rb);
        float cx = s3[1] / s3[0];
        float cy = s3[2] / s3[0];

        // --- 2.5D softmax over (depth, hw) ---
        float m2[1]; m2[0] = NEGINF;
        if (act) {
            #pragma unroll
            for (int d = 0; d < 8; d++) m2[0] = fmaxf(m2[0], l[2 + d]);
        }
        block_red<1, true>(m2, rb);
        float se = 0.0f, sez = 0.0f;
        if (act) {
            #pragma unroll
            for (int d = 0; d < 8; d++) {
                float ed = expf(l[2 + d] - m2[0]);
                se  += ed;
                sez += ed * ((float)d * inv7);
            }
        }
        float s5[5] = { se, se * xsv, se * ysv, sez, act ? (l[0] * se) : 0.0f };
        block_red<5, false>(s5, rb);
        float X = s5[1] / s5[0];
        float Y = s5[2] / s5[0];
        float Z = s5[3] / s5[0];
        float U = s5[4] / s5[0];
        float up = fmaxf(U, 0.0f) + log1pf(expf(-fabsf(U)));   // softplus

        if (t == 0) {
            int gp = n * Pp + p0 + pi;
            // coords2d (n,p,2)
            out[gp * 2 + 0] = X;
            out[gp * 2 + 1] = Y;
            // coords3d (n,p,3)
            out[Nn * Pp * 2 + gp * 3 + 0] = cx;
            out[Nn * Pp * 2 + gp * 3 + 1] = cy;
            out[Nn * Pp * 2 + gp * 3 + 2] = Z;
            // uncertainties (n,p)
            out[Nn * Pp * 5 + gp] = up;
        }
    }
}

// =====================================================================
extern "C" void kernel_launch(void* const* d_in, const int* in_sizes, int n_in,
                              void* d_out, int out_size)
{
    const float* features = (const float*)d_in[0];
    const float* weights  = (const float*)d_in[1];
    const float* conv_w   = (const float*)d_in[2];
    const float* gamma    = (const float*)d_in[3];
    const float* beta     = (const float*)d_in[4];
    const float* mean     = (const float*)d_in[5];
    const float* var      = (const float*)d_in[6];
    float* out = (float*)d_out;

    conv_bn_silu_kernel<<<dim3(16, 16), 256>>>(features, conv_w, gamma, beta, mean, var);

    cudaFuncSetAttribute(head_kernel,
                         cudaFuncAttributeMaxDynamicSharedMemorySize,
                         SMEM2_BYTES);
    head_kernel<<<dim3((Pp + 3) / 4, Nn), 128, SMEM2_BYTES>>>(weights, out);
}

// round 2
// speedup vs baseline: 1.3159x; 1.3159x over previous
#include <cuda_runtime.h>
#include <math.h>
#include <stdint.h>

#define Nn   16
#define Pp   866
#define CIN  1280
#define Cc   512
#define HWs  64
#define NOUT 10
#define PW   5130          // (Cc+1)*NOUT
#define BN_EPS 0.001f
#define PTILE 16
#define NPT  55            // ceil(866/16)

typedef unsigned long long ull;

__device__ __align__(16) float g_f[Nn * Cc * HWs];

// ---------- f32x2 helpers ----------
__device__ __forceinline__ ull splat2(float x) {
    ull r; asm("mov.b64 %0, {%1, %1};" : "=l"(r) : "f"(x)); return r;
}
__device__ __forceinline__ ull pack2(float lo, float hi) {
    ull r; asm("mov.b64 %0, {%1, %2};" : "=l"(r) : "f"(lo), "f"(hi)); return r;
}
__device__ __forceinline__ void fma2(ull &d, ull a, ull b) {
    asm("fma.rn.f32x2 %0, %1, %2, %0;" : "+l"(d) : "l"(a), "l"(b));
}
__device__ __forceinline__ void add2(ull &d, ull a) {
    asm("add.rn.f32x2 %0, %0, %1;" : "+l"(d) : "l"(a));
}
__device__ __forceinline__ float2 unpack2(ull u) {
    float2 f; asm("mov.b64 {%0, %1}, %2;" : "=f"(f.x), "=f"(f.y) : "l"(u)); return f;
}

__device__ __forceinline__ void cp8(void* dst, const void* src) {
    uint32_t d = (uint32_t)__cvta_generic_to_shared(dst);
    asm volatile("cp.async.ca.shared.global [%0], [%1], 8;" :: "r"(d), "l"(src));
}
#define CP_COMMIT() asm volatile("cp.async.commit_group;")
#define CP_WAIT0()  asm volatile("cp.async.wait_group 0;")

// ---------- width-16 reductions ----------
__device__ __forceinline__ float rmax16(float v) {
    #pragma unroll
    for (int o = 8; o > 0; o >>= 1)
        v = fmaxf(v, __shfl_xor_sync(0xffffffffu, v, o));
    return v;
}
__device__ __forceinline__ float rsum16(float v) {
    #pragma unroll
    for (int o = 8; o > 0; o >>= 1)
        v += __shfl_xor_sync(0xffffffffu, v, o);
    return v;
}

// =====================================================================
// Kernel 1: conv 1x1 + BN + SiLU  ->  g_f[n][c][hw]
// grid (8 ctiles of 64c, 16 n), 256 threads = 32 hw-pairs x 8 cgroups(8c)
// thread tile: 8 c (4 f32x2 pairs) x 2 hw
// =====================================================================
__global__ void __launch_bounds__(256)
conv_kernel(const float* __restrict__ feat,
            const float* __restrict__ convw,
            const float* __restrict__ gamma,
            const float* __restrict__ beta,
            const float* __restrict__ mean,
            const float* __restrict__ var)
{
    const int n  = blockIdx.y;
    const int cb = blockIdx.x * 64;
    const int t  = threadIdx.x;
    const int cs  = t & 31;     // hw pair index: hw = cs*2
    const int csl = t >> 5;     // 0..7 : channels cb + csl*8 ..

    __shared__ float sW[32 * 64];   // [k][c] for current chunk

    ull acc[4][2];
    #pragma unroll
    for (int i = 0; i < 4; i++) { acc[i][0] = 0ull; acc[i][1] = 0ull; }

    // staging mapping: c = t>>2 (0..63), q = t&3 (8 k each)
    const int stc = t >> 2;
    const int stq = t & 3;
    const float* wsrc = convw + (size_t)(cb + stc) * CIN + stq * 8;
    const float* fbase = feat + (size_t)n * CIN * HWs + cs * 2;

    float4 R0 = __ldg((const float4*)(wsrc + 0));
    float4 R1 = __ldg((const float4*)(wsrc + 4));

    for (int ch = 0; ch < CIN / 32; ch++) {
        const int kb = ch * 32;
        // store staged regs
        {
            int k0 = stq * 8;
            sW[(k0 + 0) * 64 + stc] = R0.x;
            sW[(k0 + 1) * 64 + stc] = R0.y;
            sW[(k0 + 2) * 64 + stc] = R0.z;
            sW[(k0 + 3) * 64 + stc] = R0.w;
            sW[(k0 + 4) * 64 + stc] = R1.x;
            sW[(k0 + 5) * 64 + stc] = R1.y;
            sW[(k0 + 6) * 64 + stc] = R1.z;
            sW[(k0 + 7) * 64 + stc] = R1.w;
        }
        __syncthreads();
        if (ch + 1 < CIN / 32) {
            R0 = __ldg((const float4*)(wsrc + (kb + 32) + 0));
            R1 = __ldg((const float4*)(wsrc + (kb + 32) + 4));
        }
        #pragma unroll 8
        for (int kk = 0; kk < 32; kk++) {
            float2 bv = __ldg((const float2*)(fbase + (size_t)(kb + kk) * HWs));
            ull s0 = splat2(bv.x);
            ull s1 = splat2(bv.y);
            const float* wr = sW + kk * 64 + csl * 8;
            ull a0 = *(const ull*)(wr + 0);
            ull a1 = *(const ull*)(wr + 2);
            ull a2 = *(const ull*)(wr + 4);
            ull a3 = *(const ull*)(wr + 6);
            fma2(acc[0][0], a0, s0); fma2(acc[0][1], a0, s1);
            fma2(acc[1][0], a1, s0); fma2(acc[1][1], a1, s1);
            fma2(acc[2][0], a2, s0); fma2(acc[2][1], a2, s1);
            fma2(acc[3][0], a3, s0); fma2(acc[3][1], a3, s1);
        }
        __syncthreads();
    }

    // epilogue: BN + SiLU, store as float2 per channel
    #pragma unroll
    for (int i2 = 0; i2 < 4; i2++) {
        int c0 = cb + csl * 8 + 2 * i2;
        float sc0 = __ldg(gamma + c0) * rsqrtf(__ldg(var + c0) + BN_EPS);
        float bi0 = __ldg(beta + c0) - __ldg(mean + c0) * sc0;
        float sc1 = __ldg(gamma + c0 + 1) * rsqrtf(__ldg(var + c0 + 1) + BN_EPS);
        float bi1 = __ldg(beta + c0 + 1) - __ldg(mean + c0 + 1) * sc1;
        float2 v0 = unpack2(acc[i2][0]);   // hw = cs*2   (ch c0 in .x, c0+1 in .y)
        float2 v1 = unpack2(acc[i2][1]);   // hw = cs*2+1
        float a00 = v0.x * sc0 + bi0;  a00 = a00 / (1.0f + __expf(-a00));
        float a01 = v1.x * sc0 + bi0;  a01 = a01 / (1.0f + __expf(-a01));
        float a10 = v0.y * sc1 + bi1;  a10 = a10 / (1.0f + __expf(-a10));
        float a11 = v1.y * sc1 + bi1;  a11 = a11 / (1.0f + __expf(-a11));
        float2* o0 = (float2*)(g_f + ((size_t)n * Cc + c0) * HWs + cs * 2);
        float2* o1 = (float2*)(g_f + ((size_t)n * Cc + c0 + 1) * HWs + cs * 2);
        *o0 = make_float2(a00, a01);
        *o1 = make_float2(a10, a11);
    }
}

// =====================================================================
// Kernel 2: head GEMM + epilogue
// grid (55 p-tiles, 16 n), 256 threads = 16 cs (4 hw each) x 16 ps
// thread tile: 10 j x 4 hw.  A (weights) staged via cp.async double buffer.
// smem A layout: [k 0..31][ps*12 + j] (12-float pad per p for v4 align)
// =====================================================================
#define CHW 192                      // floats per k row in sA
#define SA_CHUNK (32 * CHW)          // 6144 floats per buffer
#define SMEM2_BYTES (2 * SA_CHUNK * 4)

__global__ void __launch_bounds__(256)
head_kernel(const float* __restrict__ weights, float* __restrict__ out)
{
    const int n  = blockIdx.y;
    const int p0 = blockIdx.x * PTILE;
    const int t  = threadIdx.x;
    const int cs = t & 15;          // hw group: hw = cs*4 .. cs*4+3
    const int ps = t >> 4;          // p slot 0..15

    extern __shared__ __align__(16) float sA[];

    const int pv = p0 + ps;                 // true p (for output guard)
    const int p  = pv < Pp ? pv : (Pp - 1); // clamped p (for loads)
    const float* wrow = weights + (size_t)(n * Pp + p) * PW;

    // ---- issue chunk 0 ----
    {
        const float* srcb = wrow + cs * 20;
        float* db = sA;
        #pragma unroll
        for (int i = 0; i < 10; i++) {
            int k2 = 2 * cs + (i >= 5 ? 1 : 0);
            int jp = (i >= 5) ? (i - 5) : i;
            cp8(db + (k2 * 96 + ps * 6 + jp) * 2, srcb + 2 * i);
        }
        CP_COMMIT();
    }

    ull acc[5][4];
    #pragma unroll
    for (int j2 = 0; j2 < 5; j2++)
        #pragma unroll
        for (int c = 0; c < 4; c++) acc[j2][c] = 0ull;

    const float* gfb = g_f + (size_t)n * Cc * HWs + cs * 4;

    int buf = 0;
    for (int ch = 0; ch < 16; ch++) {
        CP_WAIT0();
        __syncthreads();
        if (ch + 1 < 16) {
            const float* srcb = wrow + (ch + 1) * 320 + cs * 20;
            float* db = sA + (buf ^ 1) * SA_CHUNK;
            #pragma unroll
            for (int i = 0; i < 10; i++) {
                int k2 = 2 * cs + (i >= 5 ? 1 : 0);
                int jp = (i >= 5) ? (i - 5) : i;
                cp8(db + (k2 * 96 + ps * 6 + jp) * 2, srcb + 2 * i);
            }
            CP_COMMIT();
        }
        const int kb = ch * 32;
        const float* ab = sA + buf * SA_CHUNK + ps * 12;
        #pragma unroll 8
        for (int kk = 0; kk < 32; kk++) {
            float4 bv = __ldg((const float4*)(gfb + (size_t)(kb + kk) * HWs));
            ull s0 = splat2(bv.x), s1 = splat2(bv.y);
            ull s2 = splat2(bv.z), s3 = splat2(bv.w);
            const float* ap = ab + kk * CHW;
            float4 q0 = *(const float4*)(ap);
            float4 q1 = *(const float4*)(ap + 4);
            float2 q2 = *(const float2*)(ap + 8);
            ull a0 = pack2(q0.x, q0.y);
            ull a1 = pack2(q0.z, q0.w);
            ull a2 = pack2(q1.x, q1.y);
            ull a3 = pack2(q1.z, q1.w);
            ull a4 = pack2(q2.x, q2.y);
            fma2(acc[0][0], a0, s0); fma2(acc[0][1], a0, s1); fma2(acc[0][2], a0, s2); fma2(acc[0][3], a0, s3);
            fma2(acc[1][0], a1, s0); fma2(acc[1][1], a1, s1); fma2(acc[1][2], a1, s2); fma2(acc[1][3], a1, s3);
            fma2(acc[2][0], a2, s0); fma2(acc[2][1], a2, s1); fma2(acc[2][2], a2, s2); fma2(acc[2][3], a2, s3);
            fma2(acc[3][0], a3, s0); fma2(acc[3][1], a3, s1); fma2(acc[3][2], a3, s2); fma2(acc[3][3], a3, s3);
            fma2(acc[4][0], a4, s0); fma2(acc[4][1], a4, s1); fma2(acc[4][2], a4, s2); fma2(acc[4][3], a4, s3);
        }
        buf ^= 1;
    }

    // ---- bias ----
    {
        const ull* b2 = (const ull*)(wrow + Cc * NOUT);
        #pragma unroll
        for (int j2 = 0; j2 < 5; j2++) {
            ull bv = __ldg(&b2[j2]);
            #pragma unroll
            for (int c = 0; c < 4; c++) add2(acc[j2][c], bv);
        }
    }

    // ---- unpack logits: l[j][c] for hw = cs*4 + c ----
    float l[10][4];
    #pragma unroll
    for (int j2 = 0; j2 < 5; j2++)
        #pragma unroll
        for (int c = 0; c < 4; c++) {
            float2 v = unpack2(acc[j2][c]);
            l[2 * j2][c]     = v.x;
            l[2 * j2 + 1][c] = v.y;
        }

    const float inv7 = 1.0f / 7.0f;
    float xv[4];
    {
        int xb = (cs & 1) * 4;
        #pragma unroll
        for (int c = 0; c < 4; c++) xv[c] = (float)(xb + c) * inv7;
    }
    const float yv = (float)(cs >> 1) * inv7;

    // ---- xy softmax (logit channel 1) -> cx, cy ----
    float mx = fmaxf(fmaxf(l[1][0], l[1][1]), fmaxf(l[1][2], l[1][3]));
    mx = rmax16(mx);
    float q0 = 0.0f, q1 = 0.0f;
    #pragma unroll
    for (int c = 0; c < 4; c++) {
        float e = __expf(l[1][c] - mx);
        q0 += e; q1 += e * xv[c];
    }
    float qy  = yv * q0;
    float den = rsum16(q0);
    float cx  = rsum16(q1) / den;
    float cy  = rsum16(qy) / den;

    // ---- 2.5D softmax over (depth 8, hw 64) ----
    float m2 = -INFINITY;
    #pragma unroll
    for (int d = 0; d < 8; d++)
        #pragma unroll
        for (int c = 0; c < 4; c++) m2 = fmaxf(m2, l[2 + d][c]);
    m2 = rmax16(m2);

    float S0 = 0.0f, S1 = 0.0f, S3 = 0.0f, S4 = 0.0f;
    #pragma unroll
    for (int c = 0; c < 4; c++) {
        float se = 0.0f, sez = 0.0f;
        #pragma unroll
        for (int d = 0; d < 8; d++) {
            float e = __expf(l[2 + d][c] - m2);
            se  += e;
            sez += e * ((float)d * inv7);
        }
        S0 += se;
        S1 += se * xv[c];
        S3 += sez;
        S4 += l[0][c] * se;
    }
    float S2 = yv * S0;
    float R0 = rsum16(S0);
    float R1 = rsum16(S1);
    float R2 = rsum16(S2);
    float R3 = rsum16(S3);
    float R4 = rsum16(S4);
    float X = R1 / R0, Y = R2 / R0, Z = R3 / R0, U = R4 / R0;
    float up = fmaxf(U, 0.0f) + log1pf(__expf(-fabsf(U)));

    if (cs == 0 && pv < Pp) {
        int gp = n * Pp + pv;
        out[gp * 2 + 0] = X;
        out[gp * 2 + 1] = Y;
        out[Nn * Pp * 2 + gp * 3 + 0] = cx;
        out[Nn * Pp * 2 + gp * 3 + 1] = cy;
        out[Nn * Pp * 2 + gp * 3 + 2] = Z;
        out[Nn * Pp * 5 + gp] = up;
    }
}

// =====================================================================
extern "C" void kernel_launch(void* const* d_in, const int* in_sizes, int n_in,
                              void* d_out, int out_size)
{
    const float* features = (const float*)d_in[0];
    const float* weights  = (const float*)d_in[1];
    const float* conv_w   = (const float*)d_in[2];
    const float* gamma    = (const float*)d_in[3];
    const float* beta     = (const float*)d_in[4];
    const float* mean     = (const float*)d_in[5];
    const float* var      = (const float*)d_in[6];
    float* out = (float*)d_out;

    conv_kernel<<<dim3(8, Nn), 256>>>(features, conv_w, gamma, beta, mean, var);

    cudaFuncSetAttribute(head_kernel,
                         cudaFuncAttributeMaxDynamicSharedMemorySize,
                         SMEM2_BYTES);
    head_kernel<<<dim3(NPT, Nn), 256, SMEM2_BYTES>>>(weights, out);
}

// round 3
// speedup vs baseline: 1.7501x; 1.3300x over previous
#include <cuda_runtime.h>
#include <math.h>
#include <stdint.h>

#define Nn   16
#define Pp   866
#define CIN  1280
#define Cc   512
#define HWs  64
#define NOUT 10
#define PW   5130          // (Cc+1)*NOUT
#define BN_EPS 0.001f
#define PTILE 16
#define NPT  55            // ceil(866/16)

typedef unsigned long long ull;

__device__ __align__(16) float g_f[Nn * Cc * HWs];

// ---------- f32x2 helpers ----------
__device__ __forceinline__ ull splat2(float x) {
    ull r; asm("mov.b64 %0, {%1, %1};" : "=l"(r) : "f"(x)); return r;
}
__device__ __forceinline__ void fma2(ull &d, ull a, ull b) {
    asm("fma.rn.f32x2 %0, %1, %2, %0;" : "+l"(d) : "l"(a), "l"(b));
}
__device__ __forceinline__ void add2(ull &d, ull a) {
    asm("add.rn.f32x2 %0, %0, %1;" : "+l"(d) : "l"(a));
}
__device__ __forceinline__ float2 unpack2(ull u) {
    float2 f; asm("mov.b64 {%0, %1}, %2;" : "=f"(f.x), "=f"(f.y) : "l"(u)); return f;
}

__device__ __forceinline__ void cp8(void* dst, const void* src) {
    uint32_t d = (uint32_t)__cvta_generic_to_shared(dst);
    asm volatile("cp.async.ca.shared.global [%0], [%1], 8;" :: "r"(d), "l"(src));
}
__device__ __forceinline__ void cp16(void* dst, const void* src) {
    uint32_t d = (uint32_t)__cvta_generic_to_shared(dst);
    asm volatile("cp.async.cg.shared.global [%0], [%1], 16;" :: "r"(d), "l"(src));
}
#define CP_COMMIT() asm volatile("cp.async.commit_group;")
#define CP_WAIT0()  asm volatile("cp.async.wait_group 0;")
#define CP_WAIT1()  asm volatile("cp.async.wait_group 1;")

// ---------- width-16 reductions ----------
__device__ __forceinline__ float rmax16(float v) {
    #pragma unroll
    for (int o = 8; o > 0; o >>= 1)
        v = fmaxf(v, __shfl_xor_sync(0xffffffffu, v, o));
    return v;
}
__device__ __forceinline__ float rsum16(float v) {
    #pragma unroll
    for (int o = 8; o > 0; o >>= 1)
        v += __shfl_xor_sync(0xffffffffu, v, o);
    return v;
}

// =====================================================================
// Kernel 1: conv 1x1 + BN + SiLU  ->  g_f[n][c][hw]
// grid (8 ctiles of 64c, 16 n), 256 thr = 32 hw-pairs x 8 cgroups(8c)
// thread tile 8c x 2hw. W reg-staged transpose; F cp.async double-buffer.
// =====================================================================
__global__ void __launch_bounds__(256)
conv_kernel(const float* __restrict__ feat,
            const float* __restrict__ convw,
            const float* __restrict__ gamma,
            const float* __restrict__ beta,
            const float* __restrict__ mean,
            const float* __restrict__ var)
{
    const int n  = blockIdx.y;
    const int cb = blockIdx.x * 64;
    const int t  = threadIdx.x;
    const int cs  = t & 31;     // hw pair index: hw = cs*2
    const int csl = t >> 5;     // 0..7 : channels cb + csl*8 ..

    __shared__ __align__(16) float sW[32 * 64];      // [k][c]
    __shared__ __align__(16) float sF[2][32 * 64];   // [k][hw] double buffer

    ull acc[4][2];
    #pragma unroll
    for (int i = 0; i < 4; i++) { acc[i][0] = 0ull; acc[i][1] = 0ull; }

    const int stc = t >> 2;                     // staging: c index 0..63
    const int stq = t & 3;                      // staging: 8-k group
    const float* wsrc = convw + (size_t)(cb + stc) * CIN + stq * 8;
    const float* fsrc = feat + (size_t)n * CIN * HWs;   // [k][hw]

    float4 R0 = __ldg((const float4*)(wsrc + 0));
    float4 R1 = __ldg((const float4*)(wsrc + 4));

    // prologue: f chunk 0
    #pragma unroll
    for (int i = 0; i < 2; i++)
        cp16(&sF[0][(t + 256 * i) * 4], fsrc + (t + 256 * i) * 4);
    CP_COMMIT();

    int buf = 0;
    const int NCH = CIN / 32;                   // 40
    for (int ch = 0; ch < NCH; ch++) {
        const int kb = ch * 32;
        // store staged W regs
        {
            int k0 = stq * 8;
            sW[(k0 + 0) * 64 + stc] = R0.x;
            sW[(k0 + 1) * 64 + stc] = R0.y;
            sW[(k0 + 2) * 64 + stc] = R0.z;
            sW[(k0 + 3) * 64 + stc] = R0.w;
            sW[(k0 + 4) * 64 + stc] = R1.x;
            sW[(k0 + 5) * 64 + stc] = R1.y;
            sW[(k0 + 6) * 64 + stc] = R1.z;
            sW[(k0 + 7) * 64 + stc] = R1.w;
        }
        if (ch + 1 < NCH) {
            const float* fs = fsrc + (kb + 32) * HWs;
            #pragma unroll
            for (int i = 0; i < 2; i++)
                cp16(&sF[buf ^ 1][(t + 256 * i) * 4], fs + (t + 256 * i) * 4);
            CP_COMMIT();
            CP_WAIT1();
        } else {
            CP_WAIT0();
        }
        __syncthreads();
        if (ch + 1 < NCH) {
            R0 = __ldg((const float4*)(wsrc + (kb + 32) + 0));
            R1 = __ldg((const float4*)(wsrc + (kb + 32) + 4));
        }
        const float* sfb = &sF[buf][cs * 2];
        #pragma unroll 8
        for (int kk = 0; kk < 32; kk++) {
            float2 bv = *(const float2*)(sfb + kk * 64);
            ull s0 = splat2(bv.x);
            ull s1 = splat2(bv.y);
            const float* wr = sW + kk * 64 + csl * 8;
            ulonglong2 w01 = *(const ulonglong2*)(wr);
            ulonglong2 w23 = *(const ulonglong2*)(wr + 4);
            fma2(acc[0][0], w01.x, s0); fma2(acc[0][1], w01.x, s1);
            fma2(acc[1][0], w01.y, s0); fma2(acc[1][1], w01.y, s1);
            fma2(acc[2][0], w23.x, s0); fma2(acc[2][1], w23.x, s1);
            fma2(acc[3][0], w23.y, s0); fma2(acc[3][1], w23.y, s1);
        }
        __syncthreads();
        buf ^= 1;
    }

    // epilogue: BN + SiLU
    #pragma unroll
    for (int i2 = 0; i2 < 4; i2++) {
        int c0 = cb + csl * 8 + 2 * i2;
        float sc0 = __ldg(gamma + c0) * rsqrtf(__ldg(var + c0) + BN_EPS);
        float bi0 = __ldg(beta + c0) - __ldg(mean + c0) * sc0;
        float sc1 = __ldg(gamma + c0 + 1) * rsqrtf(__ldg(var + c0 + 1) + BN_EPS);
        float bi1 = __ldg(beta + c0 + 1) - __ldg(mean + c0 + 1) * sc1;
        float2 v0 = unpack2(acc[i2][0]);   // hw = cs*2
        float2 v1 = unpack2(acc[i2][1]);   // hw = cs*2+1
        float a00 = v0.x * sc0 + bi0;  a00 = a00 / (1.0f + __expf(-a00));
        float a01 = v1.x * sc0 + bi0;  a01 = a01 / (1.0f + __expf(-a01));
        float a10 = v0.y * sc1 + bi1;  a10 = a10 / (1.0f + __expf(-a10));
        float a11 = v1.y * sc1 + bi1;  a11 = a11 / (1.0f + __expf(-a11));
        float2* o0 = (float2*)(g_f + ((size_t)n * Cc + c0) * HWs + cs * 2);
        float2* o1 = (float2*)(g_f + ((size_t)n * Cc + c0 + 1) * HWs + cs * 2);
        *o0 = make_float2(a00, a01);
        *o1 = make_float2(a10, a11);
    }
}

// =====================================================================
// Kernel 2: head GEMM + epilogue
// grid (55, 16), 256 thr = 16 cs (4 hw) x 16 ps. thread tile 10j x 4hw.
// A AND f both cp.async double-buffered; A read as u64 pairs (no packs).
// =====================================================================
#define CHW 192                       // floats per k row in sA (16p x 12 pad)
#define SA_CHUNK (32 * CHW)           // 6144 floats
#define SF_CHUNK (32 * HWs)           // 2048 floats
#define SMEM2_FLOATS (2 * SA_CHUNK + 2 * SF_CHUNK)   // 16384 -> 64KB
#define SMEM2_BYTES (SMEM2_FLOATS * 4)

__global__ void __launch_bounds__(256)
head_kernel(const float* __restrict__ weights, float* __restrict__ out)
{
    const int n  = blockIdx.y;
    const int p0 = blockIdx.x * PTILE;
    const int t  = threadIdx.x;
    const int cs = t & 15;          // hw group: hw = cs*4 .. cs*4+3
    const int ps = t >> 4;          // p slot 0..15

    extern __shared__ __align__(16) float smem[];
    float* sA = smem;                       // 2 x 6144
    float* sF = smem + 2 * SA_CHUNK;        // 2 x 2048

    const int pv = p0 + ps;
    const int p  = pv < Pp ? pv : (Pp - 1);
    const float* wrow = weights + (size_t)(n * Pp + p) * PW;
    const float* gfn  = g_f + (size_t)n * Cc * HWs;

    // ---- prologue: chunk 0 (A + F) ----
    {
        const float* srcb = wrow + cs * 20;
        #pragma unroll
        for (int i = 0; i < 10; i++) {
            int k2 = 2 * cs + (i >= 5 ? 1 : 0);
            int jp = (i >= 5) ? (i - 5) : i;
            cp8(sA + k2 * CHW + ps * 12 + jp * 2, srcb + 2 * i);
        }
        #pragma unroll
        for (int i = 0; i < 2; i++)
            cp16(sF + (t + 256 * i) * 4, gfn + (t + 256 * i) * 4);
        CP_COMMIT();
    }

    ull acc[5][4];
    #pragma unroll
    for (int j2 = 0; j2 < 5; j2++)
        #pragma unroll
        for (int c = 0; c < 4; c++) acc[j2][c] = 0ull;

    int buf = 0;
    for (int ch = 0; ch < 16; ch++) {
        if (ch + 1 < 16) {
            const float* srcb = wrow + (ch + 1) * 320 + cs * 20;
            float* da = sA + (buf ^ 1) * SA_CHUNK;
            #pragma unroll
            for (int i = 0; i < 10; i++) {
                int k2 = 2 * cs + (i >= 5 ? 1 : 0);
                int jp = (i >= 5) ? (i - 5) : i;
                cp8(da + k2 * CHW + ps * 12 + jp * 2, srcb + 2 * i);
            }
            const float* fs = gfn + (ch + 1) * SF_CHUNK;
            float* df = sF + (buf ^ 1) * SF_CHUNK;
            #pragma unroll
            for (int i = 0; i < 2; i++)
                cp16(df + (t + 256 * i) * 4, fs + (t + 256 * i) * 4);
            CP_COMMIT();
            CP_WAIT1();
        } else {
            CP_WAIT0();
        }
        __syncthreads();

        const float* ab  = sA + buf * SA_CHUNK + ps * 12;
        const float* fb2 = sF + buf * SF_CHUNK + cs * 4;
        #pragma unroll 8
        for (int kk = 0; kk < 32; kk++) {
            float4 bv = *(const float4*)(fb2 + kk * 64);
            ull s0 = splat2(bv.x), s1 = splat2(bv.y);
            ull s2 = splat2(bv.z), s3 = splat2(bv.w);
            const float* ap = ab + kk * CHW;
            ulonglong2 w01 = *(const ulonglong2*)(ap);
            ulonglong2 w23 = *(const ulonglong2*)(ap + 4);
            ull a4 = *(const ull*)(ap + 8);
            fma2(acc[0][0], w01.x, s0); fma2(acc[0][1], w01.x, s1); fma2(acc[0][2], w01.x, s2); fma2(acc[0][3], w01.x, s3);
            fma2(acc[1][0], w01.y, s0); fma2(acc[1][1], w01.y, s1); fma2(acc[1][2], w01.y, s2); fma2(acc[1][3], w01.y, s3);
            fma2(acc[2][0], w23.x, s0); fma2(acc[2][1], w23.x, s1); fma2(acc[2][2], w23.x, s2); fma2(acc[2][3], w23.x, s3);
            fma2(acc[3][0], w23.y, s0); fma2(acc[3][1], w23.y, s1); fma2(acc[3][2], w23.y, s2); fma2(acc[3][3], w23.y, s3);
            fma2(acc[4][0], a4,    s0); fma2(acc[4][1], a4,    s1); fma2(acc[4][2], a4,    s2); fma2(acc[4][3], a4,    s3);
        }
        __syncthreads();
        buf ^= 1;
    }

    // ---- bias ----
    {
        const ull* b2 = (const ull*)(wrow + Cc * NOUT);
        #pragma unroll
        for (int j2 = 0; j2 < 5; j2++) {
            ull bv = __ldg(&b2[j2]);
            #pragma unroll
            for (int c = 0; c < 4; c++) add2(acc[j2][c], bv);
        }
    }

    // ---- unpack logits: l[j][c] for hw = cs*4 + c ----
    float l[10][4];
    #pragma unroll
    for (int j2 = 0; j2 < 5; j2++)
        #pragma unroll
        for (int c = 0; c < 4; c++) {
            float2 v = unpack2(acc[j2][c]);
            l[2 * j2][c]     = v.x;
            l[2 * j2 + 1][c] = v.y;
        }

    const float inv7 = 1.0f / 7.0f;
    float xv[4];
    {
        int xb = (cs & 1) * 4;
        #pragma unroll
        for (int c = 0; c < 4; c++) xv[c] = (float)(xb + c) * inv7;
    }
    const float yv = (float)(cs >> 1) * inv7;

    // ---- xy softmax (channel 1) -> cx, cy ----
    float mx = fmaxf(fmaxf(l[1][0], l[1][1]), fmaxf(l[1][2], l[1][3]));
    mx = rmax16(mx);
    float q0 = 0.0f, q1 = 0.0f;
    #pragma unroll
    for (int c = 0; c < 4; c++) {
        float e = __expf(l[1][c] - mx);
        q0 += e; q1 += e * xv[c];
    }
    float qy  = yv * q0;
    float den = rsum16(q0);
    float cx  = rsum16(q1) / den;
    float cy  = rsum16(qy) / den;

    // ---- 2.5D softmax over (depth 8, hw 64) ----
    float m2 = -INFINITY;
    #pragma unroll
    for (int d = 0; d < 8; d++)
        #pragma unroll
        for (int c = 0; c < 4; c++) m2 = fmaxf(m2, l[2 + d][c]);
    m2 = rmax16(m2);

    float S0 = 0.0f, S1 = 0.0f, S3 = 0.0f, S4 = 0.0f;
    #pragma unroll
    for (int c = 0; c < 4; c++) {
        float se = 0.0f, sez = 0.0f;
        #pragma unroll
        for (int d = 0; d < 8; d++) {
            float e = __expf(l[2 + d][c] - m2);
            se  += e;
            sez += e * ((float)d * inv7);
        }
        S0 += se;
        S1 += se * xv[c];
        S3 += sez;
        S4 += l[0][c] * se;
    }
    float S2 = yv * S0;
    float R0 = rsum16(S0);
    float R1 = rsum16(S1);
    float R2 = rsum16(S2);
    float R3 = rsum16(S3);
    float R4 = rsum16(S4);
    float X = R1 / R0, Y = R2 / R0, Z = R3 / R0, U = R4 / R0;
    float up = fmaxf(U, 0.0f) + log1pf(__expf(-fabsf(U)));

    if (cs == 0 && pv < Pp) {
        int gp = n * Pp + pv;
        out[gp * 2 + 0] = X;
        out[gp * 2 + 1] = Y;
        out[Nn * Pp * 2 + gp * 3 + 0] = cx;
        out[Nn * Pp * 2 + gp * 3 + 1] = cy;
        out[Nn * Pp * 2 + gp * 3 + 2] = Z;
        out[Nn * Pp * 5 + gp] = up;
    }
}

// =====================================================================
extern "C" void kernel_launch(void* const* d_in, const int* in_sizes, int n_in,
                              void* d_out, int out_size)
{
    const float* features = (const float*)d_in[0];
    const float* weights  = (const float*)d_in[1];
    const float* conv_w   = (const float*)d_in[2];
    const float* gamma    = (const float*)d_in[3];
    const float* beta     = (const float*)d_in[4];
    const float* mean     = (const float*)d_in[5];
    const float* var      = (const float*)d_in[6];
    float* out = (float*)d_out;

    conv_kernel<<<dim3(8, Nn), 256>>>(features, conv_w, gamma, beta, mean, var);

    cudaFuncSetAttribute(head_kernel,
                         cudaFuncAttributeMaxDynamicSharedMemorySize,
                         SMEM2_BYTES);
    head_kernel<<<dim3(NPT, Nn), 256, SMEM2_BYTES>>>(weights, out);
}

// round 4
// speedup vs baseline: 2.5297x; 1.4455x over previous
#include <cuda_runtime.h>
#include <math.h>
#include <stdint.h>

#define Nn   16
#define Pp   866
#define CIN  1280
#define Cc   512
#define HWs  64
#define NOUT 10
#define PW   5130          // (Cc+1)*NOUT
#define BN_EPS 0.001f
#define PTILE 16
#define NPT  55            // ceil(866/16)

typedef unsigned long long ull;

__device__ __align__(16) float g_f[Nn * Cc * HWs];

// ---------- f32x2 helpers ----------
__device__ __forceinline__ ull splat2(float x) {
    ull r; asm("mov.b64 %0, {%1, %1};" : "=l"(r) : "f"(x)); return r;
}
__device__ __forceinline__ void fma2(ull &d, ull a, ull b) {
    asm("fma.rn.f32x2 %0, %1, %2, %0;" : "+l"(d) : "l"(a), "l"(b));
}
__device__ __forceinline__ void add2(ull &d, ull a) {
    asm("add.rn.f32x2 %0, %0, %1;" : "+l"(d) : "l"(a));
}
__device__ __forceinline__ float2 unpack2(ull u) {
    float2 f; asm("mov.b64 {%0, %1}, %2;" : "=f"(f.x), "=f"(f.y) : "l"(u)); return f;
}

__device__ __forceinline__ void cp8(void* dst, const void* src) {
    uint32_t d = (uint32_t)__cvta_generic_to_shared(dst);
    asm volatile("cp.async.ca.shared.global [%0], [%1], 8;" :: "r"(d), "l"(src));
}
__device__ __forceinline__ void cp16(void* dst, const void* src) {
    uint32_t d = (uint32_t)__cvta_generic_to_shared(dst);
    asm volatile("cp.async.cg.shared.global [%0], [%1], 16;" :: "r"(d), "l"(src));
}
#define CP_COMMIT() asm volatile("cp.async.commit_group;")
#define CP_WAIT0()  asm volatile("cp.async.wait_group 0;")
#define CP_WAIT1()  asm volatile("cp.async.wait_group 1;")

// ---------- width-16 reductions ----------
__device__ __forceinline__ float rmax16(float v) {
    #pragma unroll
    for (int o = 8; o > 0; o >>= 1)
        v = fmaxf(v, __shfl_xor_sync(0xffffffffu, v, o));
    return v;
}
__device__ __forceinline__ float rsum16(float v) {
    #pragma unroll
    for (int o = 8; o > 0; o >>= 1)
        v += __shfl_xor_sync(0xffffffffu, v, o);
    return v;
}

// =====================================================================
// Kernel 1: conv 1x1 + BN + SiLU  ->  g_f[n][c][hw]   (unchanged R3)
// =====================================================================
__global__ void __launch_bounds__(256)
conv_kernel(const float* __restrict__ feat,
            const float* __restrict__ convw,
            const float* __restrict__ gamma,
            const float* __restrict__ beta,
            const float* __restrict__ mean,
            const float* __restrict__ var)
{
    const int n  = blockIdx.y;
    const int cb = blockIdx.x * 64;
    const int t  = threadIdx.x;
    const int cs  = t & 31;     // hw pair index: hw = cs*2
    const int csl = t >> 5;     // 0..7 : channels cb + csl*8 ..

    __shared__ __align__(16) float sW[32 * 64];      // [k][c]
    __shared__ __align__(16) float sF[2][32 * 64];   // [k][hw] double buffer

    ull acc[4][2];
    #pragma unroll
    for (int i = 0; i < 4; i++) { acc[i][0] = 0ull; acc[i][1] = 0ull; }

    const int stc = t >> 2;                     // staging: c index 0..63
    const int stq = t & 3;                      // staging: 8-k group
    const float* wsrc = convw + (size_t)(cb + stc) * CIN + stq * 8;
    const float* fsrc = feat + (size_t)n * CIN * HWs;   // [k][hw]

    float4 R0 = __ldg((const float4*)(wsrc + 0));
    float4 R1 = __ldg((const float4*)(wsrc + 4));

    #pragma unroll
    for (int i = 0; i < 2; i++)
        cp16(&sF[0][(t + 256 * i) * 4], fsrc + (t + 256 * i) * 4);
    CP_COMMIT();

    int buf = 0;
    const int NCH = CIN / 32;                   // 40
    for (int ch = 0; ch < NCH; ch++) {
        const int kb = ch * 32;
        {
            int k0 = stq * 8;
            sW[(k0 + 0) * 64 + stc] = R0.x;
            sW[(k0 + 1) * 64 + stc] = R0.y;
            sW[(k0 + 2) * 64 + stc] = R0.z;
            sW[(k0 + 3) * 64 + stc] = R0.w;
            sW[(k0 + 4) * 64 + stc] = R1.x;
            sW[(k0 + 5) * 64 + stc] = R1.y;
            sW[(k0 + 6) * 64 + stc] = R1.z;
            sW[(k0 + 7) * 64 + stc] = R1.w;
        }
        if (ch + 1 < NCH) {
            const float* fs = fsrc + (kb + 32) * HWs;
            #pragma unroll
            for (int i = 0; i < 2; i++)
                cp16(&sF[buf ^ 1][(t + 256 * i) * 4], fs + (t + 256 * i) * 4);
            CP_COMMIT();
            CP_WAIT1();
        } else {
            CP_WAIT0();
        }
        __syncthreads();
        if (ch + 1 < NCH) {
            R0 = __ldg((const float4*)(wsrc + (kb + 32) + 0));
            R1 = __ldg((const float4*)(wsrc + (kb + 32) + 4));
        }
        const float* sfb = &sF[buf][cs * 2];
        #pragma unroll 8
        for (int kk = 0; kk < 32; kk++) {
            float2 bv = *(const float2*)(sfb + kk * 64);
            ull s0 = splat2(bv.x);
            ull s1 = splat2(bv.y);
            const float* wr = sW + kk * 64 + csl * 8;
            ulonglong2 w01 = *(const ulonglong2*)(wr);
            ulonglong2 w23 = *(const ulonglong2*)(wr + 4);
            fma2(acc[0][0], w01.x, s0); fma2(acc[0][1], w01.x, s1);
            fma2(acc[1][0], w01.y, s0); fma2(acc[1][1], w01.y, s1);
            fma2(acc[2][0], w23.x, s0); fma2(acc[2][1], w23.x, s1);
            fma2(acc[3][0], w23.y, s0); fma2(acc[3][1], w23.y, s1);
        }
        __syncthreads();
        buf ^= 1;
    }

    #pragma unroll
    for (int i2 = 0; i2 < 4; i2++) {
        int c0 = cb + csl * 8 + 2 * i2;
        float sc0 = __ldg(gamma + c0) * rsqrtf(__ldg(var + c0) + BN_EPS);
        float bi0 = __ldg(beta + c0) - __ldg(mean + c0) * sc0;
        float sc1 = __ldg(gamma + c0 + 1) * rsqrtf(__ldg(var + c0 + 1) + BN_EPS);
        float bi1 = __ldg(beta + c0 + 1) - __ldg(mean + c0 + 1) * sc1;
        float2 v0 = unpack2(acc[i2][0]);   // hw = cs*2
        float2 v1 = unpack2(acc[i2][1]);   // hw = cs*2+1
        float a00 = v0.x * sc0 + bi0;  a00 = a00 / (1.0f + __expf(-a00));
        float a01 = v1.x * sc0 + bi0;  a01 = a01 / (1.0f + __expf(-a01));
        float a10 = v0.y * sc1 + bi1;  a10 = a10 / (1.0f + __expf(-a10));
        float a11 = v1.y * sc1 + bi1;  a11 = a11 / (1.0f + __expf(-a11));
        float2* o0 = (float2*)(g_f + ((size_t)n * Cc + c0) * HWs + cs * 2);
        float2* o1 = (float2*)(g_f + ((size_t)n * Cc + c0 + 1) * HWs + cs * 2);
        *o0 = make_float2(a00, a01);
        *o1 = make_float2(a10, a11);
    }
}

// =====================================================================
// Kernel 2: head GEMM + epilogue
// grid (55, 16), 256 thr = 16 cs (4 hw) x 16 ps. thread tile 10j x 4hw.
// NEW A layout: sA[ps][k*12 + j] (48B rows, 16B aligned), per-ps region
// padded to 388 floats (194 f2). Staging = linear f2 copy per p:
// thread (ps, lane16) copies f2 r = lane16+16i -> dst f2 = r + r/5.
// Conflict-free STS, coalesced LDG.
// =====================================================================
#define SA_F2    3104                 // 16 ps * 194 f2 per chunk
#define SA_CHUNK 6208                 // floats per chunk buffer
#define SF_CHUNK (32 * HWs)           // 2048 floats
#define SMEM2_FLOATS (2 * SA_CHUNK + 2 * SF_CHUNK)   // 16512
#define SMEM2_BYTES (SMEM2_FLOATS * 4)               // 66048

__global__ void __launch_bounds__(256)
head_kernel(const float* __restrict__ weights, float* __restrict__ out)
{
    const int n  = blockIdx.y;
    const int p0 = blockIdx.x * PTILE;
    const int t  = threadIdx.x;
    const int cs = t & 15;          // hw group: hw = cs*4 .. cs*4+3
    const int ps = t >> 4;          // p slot 0..15

    extern __shared__ __align__(16) float smem[];
    float* sA = smem;                       // 2 x 6208
    float* sF = smem + 2 * SA_CHUNK;        // 2 x 2048

    const int pv = p0 + ps;
    const int p  = pv < Pp ? pv : (Pp - 1);
    const float* wrow = weights + (size_t)(n * Pp + p) * PW;
    const float* gfn  = g_f + (size_t)n * Cc * HWs;

    const ull* wsrc = (const ull*)wrow;     // f2 view, 8B aligned

    // ---- prologue: chunk 0 (A + F) ----
    {
        ull* da = (ull*)sA + ps * 194;
        #pragma unroll
        for (int i = 0; i < 10; i++) {
            int r = cs + 16 * i;            // 0..159
            cp8(da + r + r / 5, wsrc + r);
        }
        #pragma unroll
        for (int i = 0; i < 2; i++)
            cp16(sF + (t + 256 * i) * 4, gfn + (t + 256 * i) * 4);
        CP_COMMIT();
    }

    ull acc[5][4];
    #pragma unroll
    for (int j2 = 0; j2 < 5; j2++)
        #pragma unroll
        for (int c = 0; c < 4; c++) acc[j2][c] = 0ull;

    int buf = 0;
    for (int ch = 0; ch < 16; ch++) {
        if (ch + 1 < 16) {
            const ull* srcb = wsrc + (ch + 1) * 160;
            ull* da = (ull*)(sA + (buf ^ 1) * SA_CHUNK) + ps * 194;
            #pragma unroll
            for (int i = 0; i < 10; i++) {
                int r = cs + 16 * i;
                cp8(da + r + r / 5, srcb + r);
            }
            const float* fs = gfn + (ch + 1) * SF_CHUNK;
            float* df = sF + (buf ^ 1) * SF_CHUNK;
            #pragma unroll
            for (int i = 0; i < 2; i++)
                cp16(df + (t + 256 * i) * 4, fs + (t + 256 * i) * 4);
            CP_COMMIT();
            CP_WAIT1();
        } else {
            CP_WAIT0();
        }
        __syncthreads();

        const float* ab  = sA + buf * SA_CHUNK + ps * 388;
        const float* fb2 = sF + buf * SF_CHUNK + cs * 4;
        #pragma unroll 8
        for (int kk = 0; kk < 32; kk++) {
            float4 bv = *(const float4*)(fb2 + kk * 64);
            ull s0 = splat2(bv.x), s1 = splat2(bv.y);
            ull s2 = splat2(bv.z), s3 = splat2(bv.w);
            const float* ap = ab + kk * 12;
            ulonglong2 w01 = *(const ulonglong2*)(ap);
            ulonglong2 w23 = *(const ulonglong2*)(ap + 4);
            ull a4 = *(const ull*)(ap + 8);
            fma2(acc[0][0], w01.x, s0); fma2(acc[0][1], w01.x, s1); fma2(acc[0][2], w01.x, s2); fma2(acc[0][3], w01.x, s3);
            fma2(acc[1][0], w01.y, s0); fma2(acc[1][1], w01.y, s1); fma2(acc[1][2], w01.y, s2); fma2(acc[1][3], w01.y, s3);
            fma2(acc[2][0], w23.x, s0); fma2(acc[2][1], w23.x, s1); fma2(acc[2][2], w23.x, s2); fma2(acc[2][3], w23.x, s3);
            fma2(acc[3][0], w23.y, s0); fma2(acc[3][1], w23.y, s1); fma2(acc[3][2], w23.y, s2); fma2(acc[3][3], w23.y, s3);
            fma2(acc[4][0], a4,    s0); fma2(acc[4][1], a4,    s1); fma2(acc[4][2], a4,    s2); fma2(acc[4][3], a4,    s3);
        }
        __syncthreads();
        buf ^= 1;
    }

    // ---- bias ----
    {
        const ull* b2 = (const ull*)(wrow + Cc * NOUT);
        #pragma unroll
        for (int j2 = 0; j2 < 5; j2++) {
            ull bv = __ldg(&b2[j2]);
            #pragma unroll
            for (int c = 0; c < 4; c++) add2(acc[j2][c], bv);
        }
    }

    // ---- unpack logits: l[j][c] for hw = cs*4 + c ----
    float l[10][4];
    #pragma unroll
    for (int j2 = 0; j2 < 5; j2++)
        #pragma unroll
        for (int c = 0; c < 4; c++) {
            float2 v = unpack2(acc[j2][c]);
            l[2 * j2][c]     = v.x;
            l[2 * j2 + 1][c] = v.y;
        }

    const float inv7 = 1.0f / 7.0f;
    float xv[4];
    {
        int xb = (cs & 1) * 4;
        #pragma unroll
        for (int c = 0; c < 4; c++) xv[c] = (float)(xb + c) * inv7;
    }
    const float yv = (float)(cs >> 1) * inv7;

    // ---- xy softmax (channel 1) -> cx, cy ----
    float mx = fmaxf(fmaxf(l[1][0], l[1][1]), fmaxf(l[1][2], l[1][3]));
    mx = rmax16(mx);
    float q0 = 0.0f, q1 = 0.0f;
    #pragma unroll
    for (int c = 0; c < 4; c++) {
        float e = __expf(l[1][c] - mx);
        q0 += e; q1 += e * xv[c];
    }
    float qy  = yv * q0;
    float den = rsum16(q0);
    float cx  = rsum16(q1) / den;
    float cy  = rsum16(qy) / den;

    // ---- 2.5D softmax over (depth 8, hw 64) ----
    float m2 = -INFINITY;
    #pragma unroll
    for (int d = 0; d < 8; d++)
        #pragma unroll
        for (int c = 0; c < 4; c++) m2 = fmaxf(m2, l[2 + d][c]);
    m2 = rmax16(m2);

    float S0 = 0.0f, S1 = 0.0f, S3 = 0.0f, S4 = 0.0f;
    #pragma unroll
    for (int c = 0; c < 4; c++) {
        float se = 0.0f, sez = 0.0f;
        #pragma unroll
        for (int d = 0; d < 8; d++) {
            float e = __expf(l[2 + d][c] - m2);
            se  += e;
            sez += e * ((float)d * inv7);
        }
        S0 += se;
        S1 += se * xv[c];
        S3 += sez;
        S4 += l[0][c] * se;
    }
    float S2 = yv * S0;
    float R0 = rsum16(S0);
    float R1 = rsum16(S1);
    float R2 = rsum16(S2);
    float R3 = rsum16(S3);
    float R4 = rsum16(S4);
    float X = R1 / R0, Y = R2 / R0, Z = R3 / R0, U = R4 / R0;
    float up = fmaxf(U, 0.0f) + log1pf(__expf(-fabsf(U)));

    if (cs == 0 && pv < Pp) {
        int gp = n * Pp + pv;
        out[gp * 2 + 0] = X;
        out[gp * 2 + 1] = Y;
        out[Nn * Pp * 2 + gp * 3 + 0] = cx;
        out[Nn * Pp * 2 + gp * 3 + 1] = cy;
        out[Nn * Pp * 2 + gp * 3 + 2] = Z;
        out[Nn * Pp * 5 + gp] = up;
    }
}

// =====================================================================
extern "C" void kernel_launch(void* const* d_in, const int* in_sizes, int n_in,
                              void* d_out, int out_size)
{
    const float* features = (const float*)d_in[0];
    const float* weights  = (const float*)d_in[1];
    const float* conv_w   = (const float*)d_in[2];
    const float* gamma    = (const float*)d_in[3];
    const float* beta     = (const float*)d_in[4];
    const float* mean     = (const float*)d_in[5];
    const float* var      = (const float*)d_in[6];
    float* out = (float*)d_out;

    conv_kernel<<<dim3(8, Nn), 256>>>(features, conv_w, gamma, beta, mean, var);

    cudaFuncSetAttribute(head_kernel,
                         cudaFuncAttributeMaxDynamicSharedMemorySize,
                         SMEM2_BYTES);
    head_kernel<<<dim3(NPT, Nn), 256, SMEM2_BYTES>>>(weights, out);
}

// round 6
// speedup vs baseline: 3.2114x; 1.2695x over previous
#include <cuda_runtime.h>
#include <math.h>
#include <stdint.h>

#define Nn   16
#define Pp   866
#define CIN  1280
#define Cc   512
#define HWs  64
#define NOUT 10
#define PW   5130          // (Cc+1)*NOUT
#define BN_EPS 0.001f

typedef unsigned long long ull;
typedef unsigned int uint32;

__device__ __align__(16) float g_f[Nn * Cc * HWs];

// ---------- f32x2 helpers (conv kernel) ----------
__device__ __forceinline__ ull splat2(float x) {
    ull r; asm("mov.b64 %0, {%1, %1};" : "=l"(r) : "f"(x)); return r;
}
__device__ __forceinline__ void fma2(ull &d, ull a, ull b) {
    asm("fma.rn.f32x2 %0, %1, %2, %0;" : "+l"(d) : "l"(a), "l"(b));
}
__device__ __forceinline__ float2 unpack2(ull u) {
    float2 f; asm("mov.b64 {%0, %1}, %2;" : "=f"(f.x), "=f"(f.y) : "l"(u)); return f;
}
__device__ __forceinline__ void cp8(void* dst, const void* src) {
    uint32 d = (uint32)__cvta_generic_to_shared(dst);
    asm volatile("cp.async.ca.shared.global [%0], [%1], 8;" :: "r"(d), "l"(src));
}
__device__ __forceinline__ void cp16(void* dst, const void* src) {
    uint32 d = (uint32)__cvta_generic_to_shared(dst);
    asm volatile("cp.async.cg.shared.global [%0], [%1], 16;" :: "r"(d), "l"(src));
}
#define CP_COMMIT() asm volatile("cp.async.commit_group;")
#define CP_WAIT0()  asm volatile("cp.async.wait_group 0;")
#define CP_WAIT1()  asm volatile("cp.async.wait_group 1;")

// ---------- tf32 mma ----------
__device__ __forceinline__ void mma_tf32(float* d, uint32 a0, uint32 a1,
                                         uint32 a2, uint32 a3,
                                         uint32 b0, uint32 b1) {
    asm volatile(
        "mma.sync.aligned.m16n8k8.row.col.f32.tf32.tf32.f32 "
        "{%0,%1,%2,%3}, {%4,%5,%6,%7}, {%8,%9}, {%0,%1,%2,%3};"
        : "+f"(d[0]), "+f"(d[1]), "+f"(d[2]), "+f"(d[3])
        : "r"(a0), "r"(a1), "r"(a2), "r"(a3), "r"(b0), "r"(b1));
}
__device__ __forceinline__ uint32 fbits(float x) {
    uint32 r; asm("mov.b32 %0, %1;" : "=r"(r) : "f"(x)); return r;
}

// ---------- warp reductions (width 32) ----------
__device__ __forceinline__ float wmax(float v) {
    #pragma unroll
    for (int o = 16; o > 0; o >>= 1)
        v = fmaxf(v, __shfl_xor_sync(0xffffffffu, v, o));
    return v;
}
__device__ __forceinline__ float wsum(float v) {
    #pragma unroll
    for (int o = 16; o > 0; o >>= 1)
        v += __shfl_xor_sync(0xffffffffu, v, o);
    return v;
}

// =====================================================================
// Kernel 1: conv 1x1 + BN + SiLU  ->  g_f[n][c][hw]   (unchanged R4)
// =====================================================================
__global__ void __launch_bounds__(256)
conv_kernel(const float* __restrict__ feat,
            const float* __restrict__ convw,
            const float* __restrict__ gamma,
            const float* __restrict__ beta,
            const float* __restrict__ mean,
            const float* __restrict__ var)
{
    const int n  = blockIdx.y;
    const int cb = blockIdx.x * 64;
    const int t  = threadIdx.x;
    const int cs  = t & 31;
    const int csl = t >> 5;

    __shared__ __align__(16) float sW[32 * 64];
    __shared__ __align__(16) float sF[2][32 * 64];

    ull acc[4][2];
    #pragma unroll
    for (int i = 0; i < 4; i++) { acc[i][0] = 0ull; acc[i][1] = 0ull; }

    const int stc = t >> 2;
    const int stq = t & 3;
    const float* wsrc = convw + (size_t)(cb + stc) * CIN + stq * 8;
    const float* fsrc = feat + (size_t)n * CIN * HWs;

    float4 R0 = __ldg((const float4*)(wsrc + 0));
    float4 R1 = __ldg((const float4*)(wsrc + 4));

    #pragma unroll
    for (int i = 0; i < 2; i++)
        cp16(&sF[0][(t + 256 * i) * 4], fsrc + (t + 256 * i) * 4);
    CP_COMMIT();

    int buf = 0;
    const int NCH = CIN / 32;
    for (int ch = 0; ch < NCH; ch++) {
        const int kb = ch * 32;
        {
            int k0 = stq * 8;
            sW[(k0 + 0) * 64 + stc] = R0.x;
            sW[(k0 + 1) * 64 + stc] = R0.y;
            sW[(k0 + 2) * 64 + stc] = R0.z;
            sW[(k0 + 3) * 64 + stc] = R0.w;
            sW[(k0 + 4) * 64 + stc] = R1.x;
            sW[(k0 + 5) * 64 + stc] = R1.y;
            sW[(k0 + 6) * 64 + stc] = R1.z;
            sW[(k0 + 7) * 64 + stc] = R1.w;
        }
        if (ch + 1 < NCH) {
            const float* fs = fsrc + (kb + 32) * HWs;
            #pragma unroll
            for (int i = 0; i < 2; i++)
                cp16(&sF[buf ^ 1][(t + 256 * i) * 4], fs + (t + 256 * i) * 4);
            CP_COMMIT();
            CP_WAIT1();
        } else {
            CP_WAIT0();
        }
        __syncthreads();
        if (ch + 1 < NCH) {
            R0 = __ldg((const float4*)(wsrc + (kb + 32) + 0));
            R1 = __ldg((const float4*)(wsrc + (kb + 32) + 4));
        }
        const float* sfb = &sF[buf][cs * 2];
        #pragma unroll 8
        for (int kk = 0; kk < 32; kk++) {
            float2 bv = *(const float2*)(sfb + kk * 64);
            ull s0 = splat2(bv.x);
            ull s1 = splat2(bv.y);
            const float* wr = sW + kk * 64 + csl * 8;
            ulonglong2 w01 = *(const ulonglong2*)(wr);
            ulonglong2 w23 = *(const ulonglong2*)(wr + 4);
            fma2(acc[0][0], w01.x, s0); fma2(acc[0][1], w01.x, s1);
            fma2(acc[1][0], w01.y, s0); fma2(acc[1][1], w01.y, s1);
            fma2(acc[2][0], w23.x, s0); fma2(acc[2][1], w23.x, s1);
            fma2(acc[3][0], w23.y, s0); fma2(acc[3][1], w23.y, s1);
        }
        __syncthreads();
        buf ^= 1;
    }

    #pragma unroll
    for (int i2 = 0; i2 < 4; i2++) {
        int c0 = cb + csl * 8 + 2 * i2;
        float sc0 = __ldg(gamma + c0) * rsqrtf(__ldg(var + c0) + BN_EPS);
        float bi0 = __ldg(beta + c0) - __ldg(mean + c0) * sc0;
        float sc1 = __ldg(gamma + c0 + 1) * rsqrtf(__ldg(var + c0 + 1) + BN_EPS);
        float bi1 = __ldg(beta + c0 + 1) - __ldg(mean + c0 + 1) * sc1;
        float2 v0 = unpack2(acc[i2][0]);
        float2 v1 = unpack2(acc[i2][1]);
        float a00 = v0.x * sc0 + bi0;  a00 = a00 / (1.0f + __expf(-a00));
        float a01 = v1.x * sc0 + bi0;  a01 = a01 / (1.0f + __expf(-a01));
        float a10 = v0.y * sc1 + bi1;  a10 = a10 / (1.0f + __expf(-a10));
        float a11 = v1.y * sc1 + bi1;  a11 = a11 / (1.0f + __expf(-a11));
        float2* o0 = (float2*)(g_f + ((size_t)n * Cc + c0) * HWs + cs * 2);
        float2* o1 = (float2*)(g_f + ((size_t)n * Cc + c0 + 1) * HWs + cs * 2);
        *o0 = make_float2(a00, a01);
        *o1 = make_float2(a10, a11);
    }
}

// =====================================================================
// Kernel 2: head via tf32 mma.sync
// grid (55, 16), 320 threads = 10 warps. Per block: 16 p.
// M = 160 rows (row = pl*10 + j, no pad), warp w owns m16 tile w.
// N = 64 hw (8 n8 tiles), K = 512 (16 chunks of 32, double-buffered).
// A smem: [pl][k][j] stride 12/k-row, 388/pl (R4-proven staging).
// B smem: [k][hw] stride 68 (conflict-free frag loads).
// =====================================================================
#define PT16  16
#define NPT   55
#define KC    32
#define NKCH  16
#define SA_F  6208               // 16 * 388
#define SF_F  (KC * 68)          // 2176
#define SMEMH_BYTES ((2 * SA_F + 2 * SF_F) * 4)   // 67072

__global__ void __launch_bounds__(320, 2)
head_mma_kernel(const float* __restrict__ weights, float* __restrict__ out)
{
    const int n    = blockIdx.y;
    const int p0   = blockIdx.x * PT16;
    const int t    = threadIdx.x;
    const int warp = t >> 5;
    const int lane = t & 31;
    const int r4   = lane >> 2;     // 0..7
    const int c4   = lane & 3;      // 0..3

    extern __shared__ __align__(16) float smem[];
    // layout: sA0 [0,6208) sA1 [6208,12416) sF0 [12416,14592) sF1 [14592,16768)

    // ---- staging precompute (A: 2560 cp8 / 320 thr = 8 each) ----
    const float2* srcA[8];
    uint32 dstA[8];
    const uint32 sbase = (uint32)__cvta_generic_to_shared(smem);
    #pragma unroll
    for (int i = 0; i < 8; i++) {
        int idx = t + 320 * i;                 // 0..2559
        int pl  = idx / 160;
        int r   = idx - pl * 160;
        int p   = p0 + pl; if (p >= Pp) p = Pp - 1;
        srcA[i] = (const float2*)(weights + (size_t)(n * Pp + p) * PW) + r;
        dstA[i] = sbase + (uint32)(pl * 194 + r + r / 5) * 8;
    }
    const uint32 sAbytes = SA_F * 4;
    const uint32 fbase0  = sbase + 2 * sAbytes;
    const float* gfn = g_f + (size_t)n * Cc * HWs;

    // ---- prologue: chunk 0 ----
    {
        #pragma unroll
        for (int i = 0; i < 8; i++) {
            uint32 d = dstA[i];
            asm volatile("cp.async.ca.shared.global [%0], [%1], 8;"
                         :: "r"(d), "l"(srcA[i]) : "memory");
        }
        #pragma unroll
        for (int i = 0; i < 2; i++) {
            int idx = t + 320 * i;
            if (idx < 512) {
                int k = idx >> 4, off = idx & 15;
                uint32 d = fbase0 + (uint32)(k * 68 + off * 4) * 4;
                asm volatile("cp.async.cg.shared.global [%0], [%1], 16;"
                             :: "r"(d), "l"(gfn + k * 64 + off * 4) : "memory");
            }
        }
        CP_COMMIT();
    }

    // ---- A frag base offsets (float indices) ----
    const int m_lo = warp * 16 + r4;
    const int m_hi = m_lo + 8;
    const int pl_lo = m_lo / 10, j_lo = m_lo - pl_lo * 10;
    const int pl_hi = m_hi / 10, j_hi = m_hi - pl_hi * 10;
    const int aoff_lo = pl_lo * 388 + j_lo + c4 * 12;
    const int aoff_hi = pl_hi * 388 + j_hi + c4 * 12;
    const int boff = c4 * 68 + r4;

    float d[8][4];
    #pragma unroll
    for (int tt = 0; tt < 8; tt++)
        #pragma unroll
        for (int k = 0; k < 4; k++) d[tt][k] = 0.0f;

    int buf = 0;
    for (int ch = 0; ch < NKCH; ch++) {
        if (ch + 1 < NKCH) {
            const uint32 abytes = (buf ^ 1) ? sAbytes : 0u;
            #pragma unroll
            for (int i = 0; i < 8; i++) {
                uint32 dd = dstA[i] + abytes;
                asm volatile("cp.async.ca.shared.global [%0], [%1], 8;"
                             :: "r"(dd), "l"(srcA[i] + (ch + 1) * 160) : "memory");
            }
            const float* fs = gfn + (ch + 1) * (KC * 64);
            const uint32 fb = fbase0 + (buf ^ 1) * (SF_F * 4);
            #pragma unroll
            for (int i = 0; i < 2; i++) {
                int idx = t + 320 * i;
                if (idx < 512) {
                    int k = idx >> 4, off = idx & 15;
                    uint32 dd = fb + (uint32)(k * 68 + off * 4) * 4;
                    asm volatile("cp.async.cg.shared.global [%0], [%1], 16;"
                                 :: "r"(dd), "l"(fs + k * 64 + off * 4) : "memory");
                }
            }
            CP_COMMIT();
            CP_WAIT1();
        } else {
            CP_WAIT0();
        }
        __syncthreads();

        const float* A = smem + buf * SA_F;
        const float* B = smem + 2 * SA_F + buf * SF_F;
        #pragma unroll
        for (int s = 0; s < 4; s++) {
            uint32 a0 = fbits(A[aoff_lo + s * 96]);
            uint32 a1 = fbits(A[aoff_hi + s * 96]);
            uint32 a2 = fbits(A[aoff_lo + s * 96 + 48]);
            uint32 a3 = fbits(A[aoff_hi + s * 96 + 48]);
            const float* Bs = B + s * 8 * 68 + boff;
            #pragma unroll
            for (int tt = 0; tt < 8; tt++) {
                uint32 b0 = fbits(Bs[tt * 8]);
                uint32 b1 = fbits(Bs[tt * 8 + 4 * 68]);
                mma_tf32(d[tt], a0, a1, a2, a3, b0, b1);
            }
        }
        __syncthreads();
        buf ^= 1;
    }

    // ---- dump logits to smem: L[m][hw], stride 68 ----
    float* L = smem;
    #pragma unroll
    for (int tt = 0; tt < 8; tt++) {
        int col = tt * 8 + c4 * 2;
        *(float2*)(L + m_lo * 68 + col) = make_float2(d[tt][0], d[tt][1]);
        *(float2*)(L + m_hi * 68 + col) = make_float2(d[tt][2], d[tt][3]);
    }
    __syncthreads();

    // ---- epilogue: warps 0..7, each handles pl = warp and warp+8 ----
    if (warp < 8) {
        const float inv7 = 1.0f / 7.0f;
        const int hw0 = lane * 2;
        const float x0 = (float)(hw0 & 7) * inv7;
        const float x1 = (float)((hw0 + 1) & 7) * inv7;
        const float yv = (float)(hw0 >> 3) * inv7;

        #pragma unroll
        for (int rep = 0; rep < 2; rep++) {
            const int pl = warp + rep * 8;
            const int pv = p0 + pl;
            const int p  = (pv < Pp) ? pv : (Pp - 1);

            float bias = 0.0f;
            if (lane < 10)
                bias = __ldg(weights + (size_t)(n * Pp + p) * PW + Cc * NOUT + lane);

            float l[10][2];
            #pragma unroll
            for (int j = 0; j < 10; j++) {
                float2 v = *(const float2*)(L + (pl * 10 + j) * 68 + hw0);
                float bj = __shfl_sync(0xffffffffu, bias, j);
                l[j][0] = v.x + bj;
                l[j][1] = v.y + bj;
            }

            // xy softmax (channel 1)
            float mx = wmax(fmaxf(l[1][0], l[1][1]));
            float e0 = __expf(l[1][0] - mx);
            float e1 = __expf(l[1][1] - mx);
            float s  = wsum(e0 + e1);
            float sx = wsum(e0 * x0 + e1 * x1);
            float sy = wsum((e0 + e1) * yv);
            float cx = sx / s;
            float cy = sy / s;

            // 2.5D softmax (channels 2..9)
            float m2 = -INFINITY;
            #pragma unroll
            for (int j = 2; j < 10; j++)
                m2 = fmaxf(m2, fmaxf(l[j][0], l[j][1]));
            m2 = wmax(m2);

            float se = 0.0f, sx2 = 0.0f, sy2 = 0.0f, sz = 0.0f, su = 0.0f;
            #pragma unroll
            for (int j = 2; j < 10; j++) {
                float ea = __expf(l[j][0] - m2);
                float eb = __expf(l[j][1] - m2);
                float zs = (float)(j - 2) * inv7;
                se  += ea + eb;
                sx2 += ea * x0 + eb * x1;
                sy2 += (ea + eb) * yv;
                sz  += (ea + eb) * zs;
                su  += ea * l[0][0] + eb * l[0][1];
            }
            se  = wsum(se);
            sx2 = wsum(sx2);
            sy2 = wsum(sy2);
            sz  = wsum(sz);
            su  = wsum(su);

            if (lane == 0 && pv < Pp) {
                float X = sx2 / se, Y = sy2 / se, Z = sz / se, U = su / se;
                float up = fmaxf(U, 0.0f) + log1pf(__expf(-fabsf(U)));
                int gp = n * Pp + pv;
                out[gp * 2 + 0] = X;
                out[gp * 2 + 1] = Y;
                out[Nn * Pp * 2 + gp * 3 + 0] = cx;
                out[Nn * Pp * 2 + gp * 3 + 1] = cy;
                out[Nn * Pp * 2 + gp * 3 + 2] = Z;
                out[Nn * Pp * 5 + gp] = up;
            }
        }
    }
}

// =====================================================================
extern "C" void kernel_launch(void* const* d_in, const int* in_sizes, int n_in,
                              void* d_out, int out_size)
{
    const float* features = (const float*)d_in[0];
    const float* weights  = (const float*)d_in[1];
    const float* conv_w   = (const float*)d_in[2];
    const float* gamma    = (const float*)d_in[3];
    const float* beta     = (const float*)d_in[4];
    const float* mean     = (const float*)d_in[5];
    const float* var      = (const float*)d_in[6];
    float* out = (float*)d_out;

    conv_kernel<<<dim3(8, Nn), 256>>>(features, conv_w, gamma, beta, mean, var);

    cudaFuncSetAttribute(head_mma_kernel,
                         cudaFuncAttributeMaxDynamicSharedMemorySize,
                         SMEMH_BYTES);
    head_mma_kernel<<<dim3(NPT, Nn), 320, SMEMH_BYTES>>>(weights, out);
}